// round 12
// baseline (speedup 1.0000x reference)
#include <cuda_runtime.h>
#include <cuda_fp16.h>
#include <cstdint>
#include <math.h>

#define TOKENS 16384   // B*S
#define Dd 1024
#define Hh 2048
#define Aa 128
#define Ss 2048
#define Bb 8

// ---------------- scratch (device globals; no allocation allowed) ----------
__device__ float  g_gate  [(size_t)TOKENS * Hh];   // fp32 (silu input)
__device__ __half g_hidden[(size_t)TOKENS * Hh];
__device__ float  g_pre   [(size_t)TOKENS * Aa];   // fp32 (ln/expert input)
__device__ __half g_ain   [(size_t)TOKENS * Aa];
__device__ __half g_ainT  [(size_t)TOKENS * Aa];   // per-batch [Aa][Ss]
__device__ float  g_aoutf [(size_t)TOKENS * Aa];
__device__ __half g_aouth [(size_t)TOKENS * Aa];
__device__ __half g_adapt [(size_t)TOKENS * Aa];
__device__ __half g_abuf  [(size_t)TOKENS * Aa];
__device__ __half g_aw    [(size_t)Bb * Ss * Ss];  // 67 MB
__device__ __half g_W     [(size_t)Dd * Aa];       // w_out @ w_eproj
// fp16 copies of inputs
__device__ __half g_xh     [(size_t)TOKENS * Dd];
__device__ __half g_wuph   [(size_t)Hh * Dd];
__device__ __half g_wgateh [(size_t)Hh * Dd];
__device__ __half g_wdownh [(size_t)Dd * Hh];
__device__ __half g_wpreh  [(size_t)Aa * Dd];
__device__ __half g_wposth [(size_t)Aa * Hh];
__device__ __half g_waprojh[(size_t)Hh * Aa];
__device__ __half g_weprojT[(size_t)Aa * Hh];      // transposed
__device__ __half g_wouth  [(size_t)Dd * Hh];

// ---------------- helpers --------------------------------------------------
__device__ __forceinline__ float siluf(float x) { return x / (1.0f + __expf(-x)); }
__device__ __forceinline__ float clip5(float x) { return fminf(fmaxf(x, -5.0f), 5.0f); }

__device__ __forceinline__ unsigned smem_u32(const void* p) {
    unsigned a;
    asm("{ .reg .u64 t; cvta.to.shared.u64 t, %1; cvt.u32.u64 %0, t; }"
        : "=r"(a) : "l"(p));
    return a;
}

#define SROW 40       // padded row stride in halves (conflict-free ldmatrix)
#define STAGES 4

// =================== BIG GEMM: CTA 128x256, warp 64x64 =====================
// NT: C[M,N] = A[M,K] @ B[N,K]^T.  8 warps (2x4), 4-stage cp.async ring.
// EPI 0: acc | 1: silu(clip(acc)) | 2: silu(Ef)*acc | 3: Eh+0.1*acc | 4: Ef+0.1*acc
template <int EPI, bool OUTH>
__global__ void __launch_bounds__(256, 1)
tc_big(const __half* __restrict__ Ag, const __half* __restrict__ Bg,
       const void* __restrict__ Eg, void* __restrict__ Cg,
       int K, int lda, int ldb, int ldc,
       long long sA, long long sB, long long sC)
{
    extern __shared__ __half smem[];
    __half* sA_ = smem;                            // STAGES * 128 * SROW
    __half* sB_ = smem + STAGES * 128 * SROW;      // STAGES * 256 * SROW

    const int tid  = threadIdx.x;
    const int wid  = tid >> 5, lane = tid & 31;
    const int g    = lane >> 2, t = lane & 3;
    const int wm   = wid & 1, wn = wid >> 1;       // 2 x 4 warp grid
    const int m0   = blockIdx.y * 128, n0 = blockIdx.x * 256;

    const __half* A = Ag + (long long)blockIdx.z * sA;
    const __half* B = Bg + (long long)blockIdx.z * sB;

    float c[4][8][4];
#pragma unroll
    for (int i = 0; i < 4; i++)
#pragma unroll
        for (int j = 0; j < 8; j++)
#pragma unroll
            for (int r = 0; r < 4; r++) c[i][j][r] = 0.0f;

    const int NC = K >> 5;

    auto fill = [&](int s, int ck) {
        const int k0 = ck << 5;
#pragma unroll
        for (int i = 0; i < 2; i++) {              // A: 128 rows x 4 x 16B
            const int slot = tid + i * 256;
            const int row = slot >> 2, j = slot & 3;
            unsigned dst = smem_u32(&sA_[s * 128 * SROW + row * SROW + j * 8]);
            const __half* src = A + (long long)(m0 + row) * lda + k0 + j * 8;
            asm volatile("cp.async.ca.shared.global [%0], [%1], 16;"
                         :: "r"(dst), "l"(src));
        }
#pragma unroll
        for (int i = 0; i < 4; i++) {              // B: 256 rows x 4 x 16B
            const int slot = tid + i * 256;
            const int row = slot >> 2, j = slot & 3;
            unsigned dst = smem_u32(&sB_[s * 256 * SROW + row * SROW + j * 8]);
            const __half* src = B + (long long)(n0 + row) * ldb + k0 + j * 8;
            asm volatile("cp.async.ca.shared.global [%0], [%1], 16;"
                         :: "r"(dst), "l"(src));
        }
    };

    auto compute = [&](int s) {
        const unsigned baseA = smem_u32(&sA_[s * 128 * SROW]);
        const unsigned baseB = smem_u32(&sB_[s * 256 * SROW]);
#pragma unroll
        for (int ks = 0; ks < 2; ks++) {
            unsigned a[4][4], b[4][4];
#pragma unroll
            for (int mt = 0; mt < 4; mt++) {
                const int row = wm * 64 + mt * 16
                                + ((lane >> 3) & 1) * 8 + (lane & 7);
                const int kc  = ks * 16 + ((lane >> 4) & 1) * 8;
                unsigned addr = baseA + (unsigned)(row * SROW + kc) * 2u;
                asm volatile("ldmatrix.sync.aligned.m8n8.x4.shared.b16 "
                             "{%0,%1,%2,%3}, [%4];"
                             : "=r"(a[mt][0]), "=r"(a[mt][1]),
                               "=r"(a[mt][2]), "=r"(a[mt][3])
                             : "r"(addr));
            }
#pragma unroll
            for (int p = 0; p < 4; p++) {
                const int row = wn * 64 + p * 16
                                + ((lane >> 4) & 1) * 8 + (lane & 7);
                const int kc  = ks * 16 + ((lane >> 3) & 1) * 8;
                unsigned addr = baseB + (unsigned)(row * SROW + kc) * 2u;
                asm volatile("ldmatrix.sync.aligned.m8n8.x4.shared.b16 "
                             "{%0,%1,%2,%3}, [%4];"
                             : "=r"(b[p][0]), "=r"(b[p][1]),
                               "=r"(b[p][2]), "=r"(b[p][3])
                             : "r"(addr));
            }
#pragma unroll
            for (int mt = 0; mt < 4; mt++)
#pragma unroll
                for (int nt = 0; nt < 8; nt++) {
                    const int p = nt >> 1, q = (nt & 1) * 2;
                    asm volatile(
                        "mma.sync.aligned.m16n8k16.row.col.f32.f16.f16.f32 "
                        "{%0,%1,%2,%3}, {%4,%5,%6,%7}, {%8,%9}, {%0,%1,%2,%3};"
                        : "+f"(c[mt][nt][0]), "+f"(c[mt][nt][1]),
                          "+f"(c[mt][nt][2]), "+f"(c[mt][nt][3])
                        : "r"(a[mt][0]), "r"(a[mt][1]), "r"(a[mt][2]), "r"(a[mt][3]),
                          "r"(b[p][q]), "r"(b[p][q + 1]));
                }
        }
    };

#pragma unroll
    for (int p = 0; p < STAGES - 1; p++) {
        if (p < NC) fill(p, p);
        asm volatile("cp.async.commit_group;" ::: "memory");
    }

    for (int ck = 0; ck < NC; ck++) {
        asm volatile("cp.async.wait_group %0;" :: "n"(STAGES - 2) : "memory");
        __syncthreads();
        const int nf = ck + STAGES - 1;            // fill first, overlap compute
        if (nf < NC) fill(nf & (STAGES - 1), nf);
        asm volatile("cp.async.commit_group;" ::: "memory");
        compute(ck & (STAGES - 1));
    }

    // ---- epilogue ----
#pragma unroll
    for (int mt = 0; mt < 4; mt++) {
#pragma unroll
        for (int hf = 0; hf < 2; hf++) {
            const int r = m0 + wm * 64 + mt * 16 + g + hf * 8;
#pragma unroll
            for (int nt = 0; nt < 8; nt++) {
                const int col = n0 + wn * 64 + nt * 8 + 2 * t;
                const long long off = (long long)r * ldc + col
                                      + (long long)blockIdx.z * sC;
                float v0 = c[mt][nt][hf * 2 + 0];
                float v1 = c[mt][nt][hf * 2 + 1];
                if (EPI == 1) {
                    v0 = siluf(clip5(v0)); v1 = siluf(clip5(v1));
                } else if (EPI == 2) {
                    float2 e = *(const float2*)((const float*)Eg + off);
                    v0 *= siluf(e.x); v1 *= siluf(e.y);
                } else if (EPI == 3) {
                    __half2 e = *(const __half2*)((const __half*)Eg + off);
                    v0 = __half2float(e.x) + 0.1f * v0;
                    v1 = __half2float(e.y) + 0.1f * v1;
                } else if (EPI == 4) {
                    float2 e = *(const float2*)((const float*)Eg + off);
                    v0 = e.x + 0.1f * v0; v1 = e.y + 0.1f * v1;
                }
                if (OUTH) {
                    *(__half2*)((__half*)Cg + off) = __floats2half2_rn(v0, v1);
                } else {
                    *(float2*)((float*)Cg + off) = make_float2(v0, v1);
                }
            }
        }
    }
}
#define SMEM_BIG (STAGES * (128 + 256) * SROW * 2)   // 122880 B

// =================== small-N GEMM: CTA 64x128 (MT=2) =======================
template <int MT, int EPI, bool OUTH>
__global__ void __launch_bounds__(256, 2)
tc_gemm(const __half* __restrict__ Ag, const __half* __restrict__ Bg,
        const void* __restrict__ Eg, void* __restrict__ Cg,
        int K, int lda, int ldb, int ldc,
        long long sA, long long sB, long long sC)
{
    constexpr int TM = MT * 32;
    extern __shared__ __half smem[];
    __half* sA_ = smem;
    __half* sB_ = smem + STAGES * TM * SROW;

    const int tid  = threadIdx.x;
    const int wid  = tid >> 5, lane = tid & 31;
    const int g    = lane >> 2, t = lane & 3;
    const int wm   = wid >> 2, wn = wid & 3;
    const int m0   = blockIdx.y * TM, n0 = blockIdx.x * 128;

    const __half* A = Ag + (long long)blockIdx.z * sA;
    const __half* B = Bg + (long long)blockIdx.z * sB;

    float c[MT][4][4];
#pragma unroll
    for (int i = 0; i < MT; i++)
#pragma unroll
        for (int j = 0; j < 4; j++)
#pragma unroll
            for (int r = 0; r < 4; r++) c[i][j][r] = 0.0f;

    const int NC = K >> 5;

    auto fill = [&](int s, int ck) {
        const int k0 = ck << 5;
#pragma unroll
        for (int i = 0; i < (TM * 4) / 256; i++) {
            const int slot = tid + i * 256;
            const int row = slot >> 2, j = slot & 3;
            unsigned dst = smem_u32(&sA_[s * TM * SROW + row * SROW + j * 8]);
            const __half* src = A + (long long)(m0 + row) * lda + k0 + j * 8;
            asm volatile("cp.async.ca.shared.global [%0], [%1], 16;"
                         :: "r"(dst), "l"(src));
        }
#pragma unroll
        for (int i = 0; i < 2; i++) {
            const int slot = tid + i * 256;
            const int row = slot >> 2, j = slot & 3;
            unsigned dst = smem_u32(&sB_[s * 128 * SROW + row * SROW + j * 8]);
            const __half* src = B + (long long)(n0 + row) * ldb + k0 + j * 8;
            asm volatile("cp.async.ca.shared.global [%0], [%1], 16;"
                         :: "r"(dst), "l"(src));
        }
    };

    auto compute = [&](int s) {
        const unsigned baseA = smem_u32(&sA_[s * TM * SROW]);
        const unsigned baseB = smem_u32(&sB_[s * 128 * SROW]);
#pragma unroll
        for (int ks = 0; ks < 2; ks++) {
            unsigned a[MT][4], b[2][4];
#pragma unroll
            for (int mt = 0; mt < MT; mt++) {
                const int row = wm * (MT * 16) + mt * 16
                                + ((lane >> 3) & 1) * 8 + (lane & 7);
                const int kc  = ks * 16 + ((lane >> 4) & 1) * 8;
                unsigned addr = baseA + (unsigned)(row * SROW + kc) * 2u;
                asm volatile("ldmatrix.sync.aligned.m8n8.x4.shared.b16 "
                             "{%0,%1,%2,%3}, [%4];"
                             : "=r"(a[mt][0]), "=r"(a[mt][1]),
                               "=r"(a[mt][2]), "=r"(a[mt][3])
                             : "r"(addr));
            }
#pragma unroll
            for (int p = 0; p < 2; p++) {
                const int row = wn * 32 + p * 16 + ((lane >> 4) & 1) * 8 + (lane & 7);
                const int kc  = ks * 16 + ((lane >> 3) & 1) * 8;
                unsigned addr = baseB + (unsigned)(row * SROW + kc) * 2u;
                asm volatile("ldmatrix.sync.aligned.m8n8.x4.shared.b16 "
                             "{%0,%1,%2,%3}, [%4];"
                             : "=r"(b[p][0]), "=r"(b[p][1]),
                               "=r"(b[p][2]), "=r"(b[p][3])
                             : "r"(addr));
            }
#pragma unroll
            for (int mt = 0; mt < MT; mt++)
#pragma unroll
                for (int nt = 0; nt < 4; nt++) {
                    const int p = nt >> 1, q = (nt & 1) * 2;
                    asm volatile(
                        "mma.sync.aligned.m16n8k16.row.col.f32.f16.f16.f32 "
                        "{%0,%1,%2,%3}, {%4,%5,%6,%7}, {%8,%9}, {%0,%1,%2,%3};"
                        : "+f"(c[mt][nt][0]), "+f"(c[mt][nt][1]),
                          "+f"(c[mt][nt][2]), "+f"(c[mt][nt][3])
                        : "r"(a[mt][0]), "r"(a[mt][1]), "r"(a[mt][2]), "r"(a[mt][3]),
                          "r"(b[p][q]), "r"(b[p][q + 1]));
                }
        }
    };

#pragma unroll
    for (int p = 0; p < STAGES - 1; p++) {
        if (p < NC) fill(p, p);
        asm volatile("cp.async.commit_group;" ::: "memory");
    }

    for (int ck = 0; ck < NC; ck++) {
        asm volatile("cp.async.wait_group %0;" :: "n"(STAGES - 2) : "memory");
        __syncthreads();
        const int nf = ck + STAGES - 1;
        if (nf < NC) fill(nf & (STAGES - 1), nf);
        asm volatile("cp.async.commit_group;" ::: "memory");
        compute(ck & (STAGES - 1));
    }

#pragma unroll
    for (int mt = 0; mt < MT; mt++) {
#pragma unroll
        for (int hf = 0; hf < 2; hf++) {
            const int r = m0 + wm * (MT * 16) + mt * 16 + g + hf * 8;
#pragma unroll
            for (int nt = 0; nt < 4; nt++) {
                const int col = n0 + wn * 32 + nt * 8 + 2 * t;
                const long long off = (long long)r * ldc + col
                                      + (long long)blockIdx.z * sC;
                float v0 = c[mt][nt][hf * 2 + 0];
                float v1 = c[mt][nt][hf * 2 + 1];
                if (OUTH) {
                    *(__half2*)((__half*)Cg + off) = __floats2half2_rn(v0, v1);
                } else {
                    *(float2*)((float*)Cg + off) = make_float2(v0, v1);
                }
            }
        }
    }
}
#define SMEM_MT2 (STAGES * (64 + 128) * SROW * 2)    // 61440 B

// ---------------- fused fp32 -> fp16 conversion (weights + x) --------------
#define N4_X   ((TOKENS * (long long)Dd) / 4)
#define N4_HD  (((long long)Hh * Dd) / 4)
#define N4_AD  (((long long)Aa * Dd) / 4)
#define N4_AH  (((long long)Aa * Hh) / 4)
__global__ void cvt_all(const float* __restrict__ x,  __half* __restrict__ xo,
                        const float* __restrict__ w1, __half* __restrict__ o1,
                        const float* __restrict__ w2, __half* __restrict__ o2,
                        const float* __restrict__ w3, __half* __restrict__ o3,
                        const float* __restrict__ w4, __half* __restrict__ o4,
                        const float* __restrict__ w5, __half* __restrict__ o5,
                        const float* __restrict__ w6, __half* __restrict__ o6,
                        const float* __restrict__ w7, __half* __restrict__ o7)
{
    long long i = (long long)blockIdx.x * blockDim.x + threadIdx.x;
    const float* src; __half* dst; long long j = i;
    if      (j < N4_X)                 { src = x;  dst = xo; }
    else if ((j -= N4_X)  < N4_HD)     { src = w1; dst = o1; }
    else if ((j -= N4_HD) < N4_HD)     { src = w2; dst = o2; }
    else if ((j -= N4_HD) < N4_HD)     { src = w3; dst = o3; }
    else if ((j -= N4_HD) < N4_AD)     { src = w4; dst = o4; }
    else if ((j -= N4_AD) < N4_AH)     { src = w5; dst = o5; }
    else if ((j -= N4_AH) < N4_AH)     { src = w6; dst = o6; }
    else if ((j -= N4_AH) < N4_HD)     { src = w7; dst = o7; }
    else return;
    float4 v = ((const float4*)src)[j];
    ((__half2*)dst)[2 * j]     = __floats2half2_rn(v.x, v.y);
    ((__half2*)dst)[2 * j + 1] = __floats2half2_rn(v.z, v.w);
}
#define CVT_TOTAL4 (N4_X + 4 * N4_HD + N4_AD + 2 * N4_AH)

// ---------------- transposes ------------------------------------------------
__global__ void transpose_f2h(const float* __restrict__ in, __half* __restrict__ out,
                              int R, int C)
{
    __shared__ __half tile[32][33];
    const int c0 = blockIdx.x * 32, r0 = blockIdx.y * 32;
    const int tx = threadIdx.x, ty = threadIdx.y;
#pragma unroll
    for (int j = 0; j < 32; j += 8)
        tile[ty + j][tx] = __float2half_rn(in[(long long)(r0 + ty + j) * C + c0 + tx]);
    __syncthreads();
#pragma unroll
    for (int j = 0; j < 32; j += 8)
        out[(long long)(c0 + ty + j) * R + r0 + tx] = tile[tx][ty + j];
}

__global__ void transpose_h(const __half* __restrict__ in, __half* __restrict__ out,
                            int R, int C, long long sIn, long long sOut)
{
    __shared__ __half tile[32][33];
    const __half* ip = in + (long long)blockIdx.z * sIn;
    __half*       op = out + (long long)blockIdx.z * sOut;
    const int c0 = blockIdx.x * 32, r0 = blockIdx.y * 32;
    const int tx = threadIdx.x, ty = threadIdx.y;
#pragma unroll
    for (int j = 0; j < 32; j += 8)
        tile[ty + j][tx] = ip[(long long)(r0 + ty + j) * C + c0 + tx];
    __syncthreads();
#pragma unroll
    for (int j = 0; j < 32; j += 8)
        op[(long long)(c0 + ty + j) * R + r0 + tx] = tile[tx][ty + j];
}

// ---------------- LayerNorm over rows of length 128 (half out) -------------
__global__ void ln_kernel(const float* __restrict__ in,
                          const float* __restrict__ g,
                          const float* __restrict__ b,
                          __half* __restrict__ out)
{
    const int row = blockIdx.x;
    const int c = threadIdx.x;
    const float v = in[(long long)row * Aa + c];
    float s = v, s2 = v * v;
#pragma unroll
    for (int o = 16; o > 0; o >>= 1) {
        s  += __shfl_xor_sync(0xffffffffu, s,  o);
        s2 += __shfl_xor_sync(0xffffffffu, s2, o);
    }
    __shared__ float ps[4], ps2[4];
    const int w = c >> 5, l = c & 31;
    if (l == 0) { ps[w] = s; ps2[w] = s2; }
    __syncthreads();
    const float ts  = ps[0] + ps[1] + ps[2] + ps[3];
    const float ts2 = ps2[0] + ps2[1] + ps2[2] + ps2[3];
    const float m   = ts * (1.0f / 128.0f);
    const float var = ts2 * (1.0f / 128.0f) - m * m;
    out[(long long)row * Aa + c] =
        __float2half_rn((v - m) * rsqrtf(var + 1e-5f) * g[c] + b[c]);
}

// ---------------- expert select + a = ln(pre @ w_exp[e]^T) -----------------
__global__ void expert_kernel(const float* __restrict__ pre,
                              const float* __restrict__ ew,
                              const float* __restrict__ w_exp,
                              const float* __restrict__ eg,
                              const float* __restrict__ eb,
                              __half* __restrict__ abuf)
{
    const int token = blockIdx.x;
    const int c = threadIdx.x;

    int e = -1;
#pragma unroll
    for (int i = 0; i < 8; i++)
        if (ew[(long long)token * 8 + i] > 0.0f) e = i;

    if (e < 0) { abuf[(long long)token * Aa + c] = __float2half_rn(0.0f); return; }

    __shared__ float sp[Aa];
    sp[c] = pre[(long long)token * Aa + c];
    __syncthreads();

    const float* wrow = w_exp + ((long long)e * Aa + c) * Aa;
    float tacc = 0.0f;
#pragma unroll 8
    for (int a = 0; a < Aa; a++) tacc += sp[a] * wrow[a];

    float s = tacc, s2 = tacc * tacc;
#pragma unroll
    for (int o = 16; o > 0; o >>= 1) {
        s  += __shfl_xor_sync(0xffffffffu, s,  o);
        s2 += __shfl_xor_sync(0xffffffffu, s2, o);
    }
    __shared__ float ps[4], ps2[4];
    const int w = c >> 5, l = c & 31;
    if (l == 0) { ps[w] = s; ps2[w] = s2; }
    __syncthreads();
    const float ts  = ps[0] + ps[1] + ps[2] + ps[3];
    const float ts2 = ps2[0] + ps2[1] + ps2[2] + ps2[3];
    const float m   = ts * (1.0f / 128.0f);
    const float var = ts2 * (1.0f / 128.0f) - m * m;
    abuf[(long long)token * Aa + c] = __float2half_rn(
        (tacc - m) * rsqrtf(var + 1e-5f) * eg[(long long)e * Aa + c]
        + eb[(long long)e * Aa + c]);
}

// ---------------- launcher --------------------------------------------------
extern "C" void kernel_launch(void* const* d_in, const int* in_sizes, int n_in,
                              void* d_out, int out_size)
{
    const float* x       = (const float*)d_in[0];
    const float* ew      = (const float*)d_in[1];
    const float* w_up    = (const float*)d_in[2];
    const float* w_gate  = (const float*)d_in[3];
    const float* w_down  = (const float*)d_in[4];
    const float* w_pre   = (const float*)d_in[5];
    const float* w_post  = (const float*)d_in[6];
    const float* an_g    = (const float*)d_in[7];
    const float* an_b    = (const float*)d_in[8];
    const float* w_aproj = (const float*)d_in[9];
    const float* w_exp   = (const float*)d_in[10];
    const float* eln_g   = (const float*)d_in[11];
    const float* eln_b   = (const float*)d_in[12];
    const float* w_eproj = (const float*)d_in[13];
    const float* w_out   = (const float*)d_in[14];
    float* out = (float*)d_out;

    float *gate, *pre, *aoutf;
    __half *hidden, *ain, *ainT, *aouth, *adapt, *abuf, *aw, *Wc;
    __half *xh, *wuph, *wgateh, *wdownh, *wpreh, *wposth, *waprojh, *weprojT, *wouth;
    cudaGetSymbolAddress((void**)&gate,    g_gate);
    cudaGetSymbolAddress((void**)&hidden,  g_hidden);
    cudaGetSymbolAddress((void**)&pre,     g_pre);
    cudaGetSymbolAddress((void**)&ain,     g_ain);
    cudaGetSymbolAddress((void**)&ainT,    g_ainT);
    cudaGetSymbolAddress((void**)&aoutf,   g_aoutf);
    cudaGetSymbolAddress((void**)&aouth,   g_aouth);
    cudaGetSymbolAddress((void**)&adapt,   g_adapt);
    cudaGetSymbolAddress((void**)&abuf,    g_abuf);
    cudaGetSymbolAddress((void**)&aw,      g_aw);
    cudaGetSymbolAddress((void**)&Wc,      g_W);
    cudaGetSymbolAddress((void**)&xh,      g_xh);
    cudaGetSymbolAddress((void**)&wuph,    g_wuph);
    cudaGetSymbolAddress((void**)&wgateh,  g_wgateh);
    cudaGetSymbolAddress((void**)&wdownh,  g_wdownh);
    cudaGetSymbolAddress((void**)&wpreh,   g_wpreh);
    cudaGetSymbolAddress((void**)&wposth,  g_wposth);
    cudaGetSymbolAddress((void**)&waprojh, g_waprojh);
    cudaGetSymbolAddress((void**)&weprojT, g_weprojT);
    cudaGetSymbolAddress((void**)&wouth,   g_wouth);

    cudaFuncSetAttribute(tc_big<0, false>, cudaFuncAttributeMaxDynamicSharedMemorySize, SMEM_BIG);
    cudaFuncSetAttribute(tc_big<2, true>,  cudaFuncAttributeMaxDynamicSharedMemorySize, SMEM_BIG);
    cudaFuncSetAttribute(tc_big<1, true>,  cudaFuncAttributeMaxDynamicSharedMemorySize, SMEM_BIG);
    cudaFuncSetAttribute(tc_big<3, true>,  cudaFuncAttributeMaxDynamicSharedMemorySize, SMEM_BIG);
    cudaFuncSetAttribute(tc_big<4, false>, cudaFuncAttributeMaxDynamicSharedMemorySize, SMEM_BIG);
    cudaFuncSetAttribute(tc_gemm<2, 0, false>, cudaFuncAttributeMaxDynamicSharedMemorySize, SMEM_MT2);
    cudaFuncSetAttribute(tc_gemm<2, 0, true>,  cudaFuncAttributeMaxDynamicSharedMemorySize, SMEM_MT2);

    const dim3 blk(256);

    // #1: all fp32->fp16 conversions in one kernel
    cvt_all<<<(unsigned)((CVT_TOTAL4 + 255) / 256), 256>>>(
        x, xh, w_gate, wgateh, w_up, wuph, w_down, wdownh,
        w_pre, wpreh, w_post, wposth, w_aproj, waprojh, w_out, wouth);

    // #2: w_eproj transpose -> [Aa][Hh]
    transpose_f2h<<<dim3(Aa / 32, Hh / 32, 1), dim3(32, 8)>>>(w_eproj, weprojT, Hh, Aa);

    // #3  L1: gate(f32) = x @ w_gate^T  [16384,2048]
    tc_big<0, false><<<dim3(Hh / 256, TOKENS / 128, 1), blk, SMEM_BIG>>>(
        xh, wgateh, nullptr, gate, Dd, Dd, Dd, Hh, 0, 0, 0);

    // #4  L2: hidden(h) = silu(gate) * (x @ w_up^T)
    tc_big<2, true><<<dim3(Hh / 256, TOKENS / 128, 1), blk, SMEM_BIG>>>(
        xh, wuph, gate, hidden, Dd, Dd, Dd, Hh, 0, 0, 0);

    // #5  L3: pre(f32) = x @ w_pre^T  [16384,128]
    tc_gemm<2, 0, false><<<dim3(1, TOKENS / 64, 1), blk, SMEM_MT2>>>(
        xh, wpreh, nullptr, pre, Dd, Dd, Dd, Aa, 0, 0, 0);

    // #6  L5: aoutf = hidden @ w_post^T  [16384,128]
    tc_gemm<2, 0, false><<<dim3(1, TOKENS / 64, 1), blk, SMEM_MT2>>>(
        hidden, wposth, nullptr, aoutf, Hh, Hh, Hh, Aa, 0, 0, 0);

    ln_kernel<<<TOKENS, Aa>>>(pre, an_g, an_b, ain);
    ln_kernel<<<TOKENS, Aa>>>(aoutf, an_g, an_b, aouth);

    // L7: aw(h) = silu(clip(ain @ aout^T))  [8,2048,2048]
    tc_big<1, true><<<dim3(Ss / 256, Ss / 128, Bb), blk, SMEM_BIG>>>(
        ain, aouth, nullptr, aw, Aa, Aa, Aa, Ss,
        (long long)Ss * Aa, (long long)Ss * Aa, (long long)Ss * Ss);

    transpose_h<<<dim3(Aa / 32, Ss / 32, Bb), dim3(32, 8)>>>(
        ain, ainT, Ss, Aa, (long long)Ss * Aa, (long long)Aa * Ss);

    // L8: adapt(h) = aw @ ain  [8,2048,128]  (NT vs ainT)
    tc_gemm<2, 0, true><<<dim3(1, Ss / 64, Bb), blk, SMEM_MT2>>>(
        aw, ainT, nullptr, adapt, Ss, Ss, Ss, Aa,
        (long long)Ss * Ss, (long long)Aa * Ss, (long long)Ss * Aa);

    // L9: hidden(h) = hidden + 0.1 * adapt @ w_aproj^T
    tc_big<3, true><<<dim3(Hh / 256, TOKENS / 128, 1), blk, SMEM_BIG>>>(
        adapt, waprojh, hidden, hidden, Aa, Aa, Aa, Hh, 0, 0, 0);

    // L10: out(f32) = hidden @ w_down^T  [16384,1024]
    tc_big<0, false><<<dim3(Dd / 256, TOKENS / 128, 1), blk, SMEM_BIG>>>(
        hidden, wdownh, nullptr, out, Hh, Hh, Hh, Dd, 0, 0, 0);

    // L11: Wc(h) = w_out @ w_eproj  [Dd,Aa]  (NT vs weprojT)
    tc_gemm<2, 0, true><<<dim3(1, Dd / 64, 1), blk, SMEM_MT2>>>(
        wouth, weprojT, nullptr, Wc, Hh, Hh, Hh, Aa, 0, 0, 0);

    expert_kernel<<<TOKENS, Aa>>>(pre, ew, w_exp, eln_g, eln_b, abuf);

    // L13: out(f32) += 0.1 * abuf @ Wc^T
    tc_big<4, false><<<dim3(Dd / 256, TOKENS / 128, 1), blk, SMEM_BIG>>>(
        abuf, Wc, out, out, Aa, Aa, Aa, Dd, 0, 0, 0);
}